// round 16
// baseline (speedup 1.0000x reference)
#include <cuda_runtime.h>
#include <cuda_bf16.h>
#include <math.h>
#include <stdint.h>

#define B_   8
#define N_   8192
#define D_   512
#define H_   8
#define BN_ROWS 65536

// ---------------- scratch ----------------
__device__ __nv_bfloat16 g_Xh[(size_t)BN_ROWS * D_];
__device__ __nv_bfloat16 g_Xl[(size_t)BN_ROWS * D_];
__device__ __nv_bfloat16 g_Xth[(size_t)BN_ROWS * D_];
__device__ __nv_bfloat16 g_Xtl[(size_t)BN_ROWS * D_];
__device__ __nv_bfloat16 g_qsh[(size_t)BN_ROWS * D_];
__device__ __nv_bfloat16 g_qsl[(size_t)BN_ROWS * D_];
__device__ __nv_bfloat16 g_Bth[1536 * 512];
__device__ __nv_bfloat16 g_Btl[1536 * 512];
__device__ float g_biasC[1536];
__device__ float g_Gp[(size_t)64 * 512 * 512];
__device__ __nv_bfloat16 g_Gh[(size_t)8 * 512 * 512];
__device__ __nv_bfloat16 g_Gl[(size_t)8 * 512 * 512];
__device__ float g_P[(size_t)8 * 512 * 512];
__device__ float g_spart[128 * 4096];
__device__ float g_s[8 * 512];
__device__ float g_kvn[64 * 4096];
__device__ __nv_bfloat16 g_Mth[(size_t)B_ * 512 * 512];
__device__ __nv_bfloat16 g_Mtl[(size_t)B_ * 512 * 512];

// ---------------- helpers ----------------
__device__ __forceinline__ uint32_t smem_u32(const void* p) {
    uint32_t a;
    asm("{ .reg .u64 t; cvta.to.shared.u64 t, %1; cvt.u32.u64 %0, t; }" : "=r"(a) : "l"(p));
    return a;
}
__device__ __forceinline__ void ldsm4(uint32_t* r, uint32_t a) {
    asm volatile("ldmatrix.sync.aligned.m8n8.x4.shared.b16 {%0,%1,%2,%3}, [%4];"
                 : "=r"(r[0]), "=r"(r[1]), "=r"(r[2]), "=r"(r[3]) : "r"(a));
}
__device__ __forceinline__ void mma16816(float* c, const uint32_t* a, const uint32_t* b) {
    asm("mma.sync.aligned.m16n8k16.row.col.f32.bf16.bf16.f32 "
        "{%0,%1,%2,%3}, {%4,%5,%6,%7}, {%8,%9}, {%0,%1,%2,%3};"
        : "+f"(c[0]), "+f"(c[1]), "+f"(c[2]), "+f"(c[3])
        : "r"(a[0]), "r"(a[1]), "r"(a[2]), "r"(a[3]), "r"(b[0]), "r"(b[1]));
}
#define CPA(d, s) asm volatile("cp.async.cg.shared.global [%0], [%1], 16;" :: "r"(d), "l"(s))
#define CPC()     asm volatile("cp.async.commit_group;" ::: "memory")

__device__ __forceinline__ void split1(float x, __nv_bfloat16& h, __nv_bfloat16& l) {
    h = __float2bfloat16(x);
    l = __float2bfloat16(x - __bfloat162float(h));
}

#define AH_O 0u
#define AL_O 18432u
#define BH_O 36864u
#define BL_O 73728u
#define STAGE_B  110592u
#define DYN_SMEM (2 * 110592)

#define GA_H 0u
#define GA_L 10240u
#define GB_H 20480u
#define GB_L 30720u
#define GSTAGE_B 40960u
#define GRAM_SMEM (2 * 40960)

// =====================================================================
// prep_w
// =====================================================================
__global__ void prep_w_kernel(
    const float* __restrict__ Wq, const float* __restrict__ Wk, const float* __restrict__ Wv,
    const float* __restrict__ bq, const float* __restrict__ bk, const float* __restrict__ bv)
{
    __shared__ float tile[32][33];
    const int k0 = blockIdx.x * 32, n0g = blockIdx.y * 32;
    const float* W; const float* bias;
    if (n0g < 512)       { W = Wq; bias = bq; }
    else if (n0g < 1024) { W = Wk; bias = bk; }
    else                 { W = Wv; bias = bv; }
    const int nn0 = n0g & 511;
    const int tx = threadIdx.x, ty = threadIdx.y;
    #pragma unroll
    for (int i = 0; i < 4; ++i)
        tile[ty + i * 8][tx] = W[(size_t)(k0 + ty + i * 8) * 512 + nn0 + tx];
    __syncthreads();
    #pragma unroll
    for (int i = 0; i < 4; ++i) {
        float x = tile[tx][ty + i * 8];
        __nv_bfloat16 h, l; split1(x, h, l);
        size_t o = (size_t)(n0g + ty + i * 8) * 512 + k0 + tx;
        g_Bth[o] = h; g_Btl[o] = l;
    }
    if (blockIdx.x == 0 && ty == 0) g_biasC[n0g + tx] = bias[nn0 + tx];
}

// =====================================================================
// transpose_pack + colsum partials
// =====================================================================
__global__ __launch_bounds__(256) void transpose_pack_kernel(const float* __restrict__ X)
{
    __shared__ ushort sh[32][80];
    __shared__ ushort sl[32][80];
    __shared__ float ps[8][32];
    const int b = blockIdx.z;
    const int d0 = blockIdx.x * 32;
    const int n0 = blockIdx.y * 64;
    const int tx = threadIdx.x, ty = threadIdx.y;

    const float* Xb = X + (size_t)b * N_ * 512;
    ushort* Xh_out = reinterpret_cast<ushort*>(g_Xh);
    ushort* Xl_out = reinterpret_cast<ushort*>(g_Xl);
    float s = 0.f;
    #pragma unroll
    for (int i = 0; i < 8; ++i) {
        const int n = ty + i * 8;
        float x = Xb[(size_t)(n0 + n) * 512 + d0 + tx];
        s += x;
        __nv_bfloat16 h, l; split1(x, h, l);
        const ushort hu = __bfloat16_as_ushort(h);
        const ushort lu = __bfloat16_as_ushort(l);
        sh[tx][n] = hu;
        sl[tx][n] = lu;
        const size_t on = ((size_t)b * N_ + n0 + n) * 512 + d0 + tx;
        Xh_out[on] = hu;
        Xl_out[on] = lu;
    }
    ps[ty][tx] = s;
    __syncthreads();

    const int t = ty * 32 + tx;
    const int d = t >> 3;
    const int ng = t & 7;
    uint4 hv = *reinterpret_cast<const uint4*>(&sh[d][ng * 8]);
    uint4 lv = *reinterpret_cast<const uint4*>(&sl[d][ng * 8]);
    const size_t o = ((size_t)b * 512 + d0 + d) * N_ + n0 + ng * 8;
    *reinterpret_cast<uint4*>(&g_Xth[o]) = hv;
    *reinterpret_cast<uint4*>(&g_Xtl[o]) = lv;

    if (ty == 0) {
        float cs = 0.f;
        #pragma unroll
        for (int j = 0; j < 8; ++j) cs += ps[j][tx];
        g_spart[(size_t)blockIdx.y * 4096 + b * 512 + d0 + tx] = cs;
    }
}

// =====================================================================
// colsum_reduce
// =====================================================================
__global__ __launch_bounds__(256) void colsum_reduce_kernel()
{
    const int out = blockIdx.x * 256 + threadIdx.x;
    float s = 0.f;
    #pragma unroll 8
    for (int j = 0; j < 128; ++j) s += g_spart[(size_t)j * 4096 + out];
    g_s[out] = s;
}

// =====================================================================
// 128x128 gemm: stage loader + core (warp 64x32, k-chunk 32)
// =====================================================================
__device__ __forceinline__ void gstage_load(
    uint32_t sdst,
    const __nv_bfloat16* __restrict__ Ah, const __nv_bfloat16* __restrict__ Al,
    const __nv_bfloat16* __restrict__ Bh, const __nv_bfloat16* __restrict__ Bl,
    int tid, int m0, int n0, int k0, size_t lda, size_t ldb)
{
    #pragma unroll
    for (int j = 0; j < 2; ++j) {
        const int idx = tid + j * 256;
        const int row = idx >> 2, seg = idx & 3;
        const uint32_t d = sdst + (uint32_t)row * 80u + (uint32_t)seg * 16u;
        CPA(d + GA_H, Ah + (size_t)(m0 + row) * lda + k0 + seg * 8);
        CPA(d + GA_L, Al + (size_t)(m0 + row) * lda + k0 + seg * 8);
        CPA(d + GB_H, Bh + (size_t)(n0 + row) * ldb + k0 + seg * 8);
        CPA(d + GB_L, Bl + (size_t)(n0 + row) * ldb + k0 + seg * 8);
    }
}

__device__ __forceinline__ void gemm128_core(
    uint32_t sb, float acc[4][4][4],
    const __nv_bfloat16* Ah, const __nv_bfloat16* Al,
    const __nv_bfloat16* Bh, const __nv_bfloat16* Bl,
    int tid, int m0, int n0, int kbase, int nch, size_t lda, size_t ldb)
{
    const int lane = tid & 31, warp = tid >> 5;
    const int wm = warp >> 2, wn = warp & 3;
    const int a_r  = lane & 15;
    const int a_c  = (lane >> 4) << 3;
    const int bg   = lane >> 3;
    const int b_nr = ((bg & 2) << 2) + (lane & 7);
    const int b_ka = (bg & 1) << 3;

    gstage_load(sb, Ah, Al, Bh, Bl, tid, m0, n0, kbase, lda, ldb);
    CPC();

    #pragma unroll 1
    for (int c = 0; c < nch; ++c) {
        if (c < nch - 1) {
            gstage_load(sb + (uint32_t)((c + 1) & 1) * GSTAGE_B, Ah, Al, Bh, Bl,
                        tid, m0, n0, kbase + (c + 1) * 32, lda, ldb);
            CPC();
            asm volatile("cp.async.wait_group 1;" ::: "memory");
        } else {
            asm volatile("cp.async.wait_group 0;" ::: "memory");
        }
        __syncthreads();

        const uint32_t s0 = sb + (uint32_t)(c & 1) * GSTAGE_B;
        #pragma unroll
        for (int ks = 0; ks < 2; ++ks) {
            uint32_t ah[4][4], al[4][4];
            #pragma unroll
            for (int mt = 0; mt < 4; ++mt) {
                const uint32_t aoff = (uint32_t)((wm * 64 + mt * 16 + a_r) * 80
                                                 + (ks * 16 + a_c) * 2);
                ldsm4(ah[mt], s0 + GA_H + aoff);
                ldsm4(al[mt], s0 + GA_L + aoff);
            }
            #pragma unroll
            for (int g = 0; g < 2; ++g) {
                const uint32_t boff = (uint32_t)((wn * 32 + g * 16 + b_nr) * 80
                                                 + (ks * 16 + b_ka) * 2);
                uint32_t bh4[4], bl4[4];
                ldsm4(bh4, s0 + GB_H + boff);
                ldsm4(bl4, s0 + GB_L + boff);
                #pragma unroll
                for (int mt = 0; mt < 4; ++mt) {
                    mma16816(acc[mt][2 * g],     ah[mt], bh4);
                    mma16816(acc[mt][2 * g + 1], ah[mt], bh4 + 2);
                }
                #pragma unroll
                for (int mt = 0; mt < 4; ++mt) {
                    mma16816(acc[mt][2 * g],     ah[mt], bl4);
                    mma16816(acc[mt][2 * g + 1], ah[mt], bl4 + 2);
                }
                #pragma unroll
                for (int mt = 0; mt < 4; ++mt) {
                    mma16816(acc[mt][2 * g],     al[mt], bh4);
                    mma16816(acc[mt][2 * g + 1], al[mt], bh4 + 2);
                }
            }
        }
        __syncthreads();
    }
}

// =====================================================================
// gram2: triangular 128x128 tiles, 2 CTAs/SM. grid 640 flat.
// =====================================================================
__global__ __launch_bounds__(256, 2) void gram2_kernel()
{
    extern __shared__ char smem[];
    const uint32_t sb = smem_u32(smem);
    const int tid = threadIdx.x, lane = tid & 31, warp = tid >> 5;
    const int wm = warp >> 2, wn = warp & 3;

    const int g = blockIdx.x;
    const int b = g / 80;
    const int rem = g - b * 80;
    const int ksp = rem / 10;
    const int ti = rem - ksp * 10;
    int tym = 0;
    while ((tym + 1) * (tym + 2) / 2 <= ti) ++tym;
    const int txm = ti - tym * (tym + 1) / 2;
    const int m0 = tym * 128, n0 = txm * 128;
    const bool mirror = (tym != txm);

    const __nv_bfloat16* Xh = g_Xth + (size_t)b * 512 * 8192;
    const __nv_bfloat16* Xl = g_Xtl + (size_t)b * 512 * 8192;
    float* gpout = g_Gp + (size_t)(b * 8 + ksp) * 262144;

    float acc[4][4][4];
    #pragma unroll
    for (int i = 0; i < 4; ++i)
        #pragma unroll
        for (int j = 0; j < 4; ++j)
            #pragma unroll
            for (int u = 0; u < 4; ++u) acc[i][j][u] = 0.f;

    gemm128_core(sb, acc, Xh, Xl, Xh, Xl, tid, m0, n0, ksp * 1024, 32, 8192, 8192);

    const int r0 = m0 + wm * 64 + (lane >> 2);
    const int cg0 = n0 + wn * 32 + (lane & 3) * 2;
    #pragma unroll
    for (int mt = 0; mt < 4; ++mt) {
        #pragma unroll
        for (int nt = 0; nt < 4; ++nt) {
            const int rr = r0 + mt * 16;
            const int cc = cg0 + nt * 8;
            float* dst = gpout + (size_t)rr * 512 + cc;
            *reinterpret_cast<float2*>(dst) = make_float2(acc[mt][nt][0], acc[mt][nt][1]);
            *reinterpret_cast<float2*>(dst + 8 * 512) = make_float2(acc[mt][nt][2], acc[mt][nt][3]);
            if (mirror) {
                gpout[(size_t)cc * 512 + rr]           = acc[mt][nt][0];
                gpout[(size_t)(cc + 1) * 512 + rr]     = acc[mt][nt][1];
                gpout[(size_t)cc * 512 + rr + 8]       = acc[mt][nt][2];
                gpout[(size_t)(cc + 1) * 512 + rr + 8] = acc[mt][nt][3];
            }
        }
    }
}

// =====================================================================
// q_gemm: q projection + fused cross-warp norm. grid 2048 flat, 2 CTAs/SM.
// =====================================================================
__global__ __launch_bounds__(256, 2) void q_gemm_kernel(const float* __restrict__ gammaIn)
{
    extern __shared__ char smem[];
    const uint32_t sb = smem_u32(smem);
    const int tid = threadIdx.x, lane = tid & 31, warp = tid >> 5;
    const int wm = warp >> 2, wn = warp & 3;

    const int idx = blockIdx.x;
    const int m0 = (idx >> 2) * 128, n0 = (idx & 3) * 128;

    float acc[4][4][4];
    #pragma unroll
    for (int i = 0; i < 4; ++i)
        #pragma unroll
        for (int j = 0; j < 4; ++j)
            #pragma unroll
            for (int u = 0; u < 4; ++u) acc[i][j][u] = 0.f;

    gemm128_core(sb, acc, g_Xh, g_Xl, g_Bth, g_Btl, tid, m0, n0, 0, 16, 512, 512);

    float* part = reinterpret_cast<float*>(smem);
    const float gam = gammaIn[(n0 + wn * 32) >> 6];
    const int r_l = lane >> 2;
    const int cg0 = n0 + wn * 32 + (lane & 3) * 2;
    float sums[8], sc_arr[8];
    #pragma unroll
    for (int mt = 0; mt < 4; ++mt) {
        #pragma unroll
        for (int z = 0; z < 2; ++z) {
            float s = 0.f;
            #pragma unroll
            for (int nt = 0; nt < 4; ++nt) {
                const int cc = cg0 + nt * 8;
                float x0 = acc[mt][nt][2 * z]     + g_biasC[cc];
                float x1 = acc[mt][nt][2 * z + 1] + g_biasC[cc + 1];
                acc[mt][nt][2 * z] = x0; acc[mt][nt][2 * z + 1] = x1;
                s = fmaf(x0, x0, s); s = fmaf(x1, x1, s);
            }
            s += __shfl_xor_sync(0xffffffffu, s, 1);
            s += __shfl_xor_sync(0xffffffffu, s, 2);
            sums[mt * 2 + z] = s;
        }
    }
    #pragma unroll
    for (int mt = 0; mt < 4; ++mt)
        #pragma unroll
        for (int z = 0; z < 2; ++z)
            if ((lane & 3) == 0) {
                const int rt = wm * 64 + mt * 16 + z * 8 + r_l;
                part[rt * 4 + wn] = sums[mt * 2 + z];
            }
    __syncthreads();
    #pragma unroll
    for (int mt = 0; mt < 4; ++mt)
        #pragma unroll
        for (int z = 0; z < 2; ++z) {
            const int rt = wm * 64 + mt * 16 + z * 8 + r_l;
            const float s2 = part[rt * 4 + wn] + part[rt * 4 + (wn ^ 1)];
            sc_arr[mt * 2 + z] = gam / sqrtf(s2);
        }
    #pragma unroll
    for (int mt = 0; mt < 4; ++mt) {
        #pragma unroll
        for (int z = 0; z < 2; ++z) {
            const int rr = m0 + wm * 64 + mt * 16 + z * 8 + r_l;
            const float sc = sc_arr[mt * 2 + z];
            #pragma unroll
            for (int nt = 0; nt < 4; ++nt) {
                __nv_bfloat16 h0, l0, h1, l1;
                split1(acc[mt][nt][2 * z] * sc, h0, l0);
                split1(acc[mt][nt][2 * z + 1] * sc, h1, l1);
                const uint32_t hw = (uint32_t)__bfloat16_as_ushort(h0)
                                  | ((uint32_t)__bfloat16_as_ushort(h1) << 16);
                const uint32_t lw = (uint32_t)__bfloat16_as_ushort(l0)
                                  | ((uint32_t)__bfloat16_as_ushort(l1) << 16);
                const size_t o = (size_t)rr * 512 + cg0 + nt * 8;
                *reinterpret_cast<uint32_t*>(&g_qsh[o]) = hw;
                *reinterpret_cast<uint32_t*>(&g_qsl[o]) = lw;
            }
        }
    }
}

// =====================================================================
// p_gemm: P = G @ Wv, 128x128, 2 CTAs/SM. grid (4, 32)
// =====================================================================
__global__ __launch_bounds__(256, 2) void p_gemm_kernel()
{
    extern __shared__ char smem[];
    const uint32_t sb = smem_u32(smem);
    const int tid = threadIdx.x, lane = tid & 31, warp = tid >> 5;
    const int wm = warp >> 2, wn = warp & 3;
    const int m0 = blockIdx.y * 128, n0 = blockIdx.x * 128;

    const __nv_bfloat16* Bh = g_Bth + (size_t)1024 * 512;
    const __nv_bfloat16* Bl = g_Btl + (size_t)1024 * 512;

    float acc[4][4][4];
    #pragma unroll
    for (int i = 0; i < 4; ++i)
        #pragma unroll
        for (int j = 0; j < 4; ++j)
            #pragma unroll
            for (int u = 0; u < 4; ++u) acc[i][j][u] = 0.f;

    gemm128_core(sb, acc, g_Gh, g_Gl, Bh, Bl, tid, m0, n0, 0, 16, 512, 512);

    const int r0 = m0 + wm * 64 + (lane >> 2);
    const int cg0 = n0 + wn * 32 + (lane & 3) * 2;
    #pragma unroll
    for (int mt = 0; mt < 4; ++mt) {
        #pragma unroll
        for (int nt = 0; nt < 4; ++nt) {
            const int rr = r0 + mt * 16;
            const int cc = cg0 + nt * 8;
            float* dst = g_P + (size_t)rr * 512 + cc;
            *reinterpret_cast<float2*>(dst) = make_float2(acc[mt][nt][0], acc[mt][nt][1]);
            *reinterpret_cast<float2*>(dst + 8 * 512) = make_float2(acc[mt][nt][2], acc[mt][nt][3]);
        }
    }
}

// =====================================================================
// gram_reduce
// =====================================================================
__global__ __launch_bounds__(256) void gram_reduce_kernel()
{
    const size_t gid = (size_t)blockIdx.x * 256 + threadIdx.x;
    const int b = (int)(gid >> 16);
    const size_t e = (gid & 65535) * 4;
    float4 s = make_float4(0.f, 0.f, 0.f, 0.f);
    #pragma unroll
    for (int p = 0; p < 8; ++p) {
        float4 t = *reinterpret_cast<const float4*>(
            &g_Gp[((size_t)(b * 8 + p)) * 262144 + e]);
        s.x += t.x; s.y += t.y; s.z += t.z; s.w += t.w;
    }
    __nv_bfloat16 h0, l0, h1, l1, h2, l2, h3, l3;
    split1(s.x, h0, l0); split1(s.y, h1, l1); split1(s.z, h2, l2); split1(s.w, h3, l3);
    uint2 hv, lv;
    hv.x = (uint32_t)__bfloat16_as_ushort(h0) | ((uint32_t)__bfloat16_as_ushort(h1) << 16);
    hv.y = (uint32_t)__bfloat16_as_ushort(h2) | ((uint32_t)__bfloat16_as_ushort(h3) << 16);
    lv.x = (uint32_t)__bfloat16_as_ushort(l0) | ((uint32_t)__bfloat16_as_ushort(l1) << 16);
    lv.y = (uint32_t)__bfloat16_as_ushort(l2) | ((uint32_t)__bfloat16_as_ushort(l3) << 16);
    const size_t o = (size_t)b * 262144 + e;
    *reinterpret_cast<uint2*>(&g_Gh[o]) = hv;
    *reinterpret_cast<uint2*>(&g_Gl[o]) = lv;
}

// =====================================================================
// kvA
// =====================================================================
__global__ __launch_bounds__(256) void kvA_kernel(
    const float* __restrict__ Wk, const float* __restrict__ Wv,
    const float* __restrict__ bk, const float* __restrict__ bv)
{
    __shared__ float wk_s[16][68];
    __shared__ float p_s[16][68];
    __shared__ float kvs[64][65];
    __shared__ float rs[64];
    __shared__ float corr_k[64];
    __shared__ float corr_v[64];
    __shared__ float cpart[256];

    const int bh = blockIdx.x, b = bh >> 3, h = bh & 7;
    const int tid = threadIdx.x;
    const int tx = tid & 15, ty = tid >> 4;
    const int lr = tid >> 4, lc4 = (tid & 15) << 2;

    float acc[4][4];
    #pragma unroll
    for (int i = 0; i < 4; ++i)
        #pragma unroll
        for (int j = 0; j < 4; ++j) acc[i][j] = 0.f;

    for (int k0 = 0; k0 < 512; k0 += 16) {
        *reinterpret_cast<float4*>(&wk_s[lr][lc4]) =
            *reinterpret_cast<const float4*>(&Wk[(size_t)(k0 + lr) * 512 + h * 64 + lc4]);
        *reinterpret_cast<float4*>(&p_s[lr][lc4]) =
            *reinterpret_cast<const float4*>(&g_P[((size_t)b * 512 + k0 + lr) * 512 + h * 64 + lc4]);
        __syncthreads();
        #pragma unroll
        for (int kk = 0; kk < 16; ++kk) {
            float a[4], w[4];
            #pragma unroll
            for (int i = 0; i < 4; ++i) a[i] = wk_s[kk][ty * 4 + i];
            #pragma unroll
            for (int j = 0; j < 4; ++j) w[j] = p_s[kk][tx * 4 + j];
            #pragma unroll
            for (int i = 0; i < 4; ++i)
                #pragma unroll
                for (int j = 0; j < 4; ++j) acc[i][j] = fmaf(a[i], w[j], acc[i][j]);
        }
        __syncthreads();
    }

    {
        const int out = tid & 127;
        const int half = tid >> 7;
        const int idx = out & 63;
        const float* Wx = (out < 64) ? Wk : Wv;
        float s = 0.f;
        const int d0 = half * 256;
        for (int d = d0; d < d0 + 256; ++d)
            s = fmaf(g_s[b * 512 + d], Wx[(size_t)d * 512 + h * 64 + idx], s);
        cpart[half * 128 + out] = s;
    }
    __syncthreads();
    if (tid < 64) corr_k[tid] = cpart[tid] + cpart[128 + tid];
    else if (tid < 128) corr_v[tid - 64] = cpart[tid] + cpart[128 + tid];
    __syncthreads();

    #pragma unroll
    for (int i = 0; i < 4; ++i) {
        const int dk = ty * 4 + i;
        const float bkk = bk[h * 64 + dk];
        const float ck = corr_k[dk];
        #pragma unroll
        for (int j = 0; j < 4; ++j) {
            const int dv = tx * 4 + j;
            const float bvv = bv[h * 64 + dv];
            kvs[dk][dv] = acc[i][j] + ck * bvv + bkk * (corr_v[dv] + 8192.0f * bvv);
        }
    }
    __syncthreads();

    if (tid < 64) {
        float s = 0.f;
        #pragma unroll
        for (int c = 0; c < 64; ++c) { float x = kvs[tid][c]; s = fmaf(x, x, s); }
        rs[tid] = 1.0f / sqrtf(s);
    }
    __syncthreads();

    for (int idx = tid; idx < 4096; idx += 256) {
        const int dk = idx >> 6, dv = idx & 63;
        g_kvn[(size_t)bh * 4096 + idx] = kvs[dk][dv] * rs[dk];
    }
}

// =====================================================================
// kvB
// =====================================================================
__global__ __launch_bounds__(256) void kvB_kernel(
    const float* __restrict__ Wo, const float* __restrict__ gamma)
{
    extern __shared__ float dsm[];
    float (*kvn)[65] = reinterpret_cast<float(*)[65]>(dsm);
    float (*wos)[65] = reinterpret_cast<float(*)[65]>(dsm + 4160);
    float (*mts)[65] = reinterpret_cast<float(*)[65]>(dsm + 8320);

    const int bh = blockIdx.x, b = bh >> 3, h = bh & 7;
    const int dt = blockIdx.y;
    const int d0 = dt * 64;
    const int tid = threadIdx.x;
    const int tx = tid & 15, ty = tid >> 4;
    const float gam = gamma[h];

    for (int idx = tid; idx < 4096; idx += 256) {
        kvn[idx >> 6][idx & 63] = g_kvn[(size_t)bh * 4096 + idx] * gam;
        const int dv = idx >> 6, dd = idx & 63;
        wos[dv][dd] = Wo[(size_t)(h * 64 + dv) * 512 + d0 + dd];
    }
    __syncthreads();

    float a2[4][4];
    #pragma unroll
    for (int i = 0; i < 4; i++)
        #pragma unroll
        for (int j = 0; j < 4; j++) a2[i][j] = 0.f;

    #pragma unroll 8
    for (int dv = 0; dv < 64; dv++) {
        float a[4], w[4];
        #pragma unroll
        for (int i = 0; i < 4; i++) a[i] = kvn[ty * 4 + i][dv];
        #pragma unroll
        for (int j = 0; j < 4; j++) w[j] = wos[dv][tx * 4 + j];
        #pragma unroll
        for (int i = 0; i < 4; i++)
            #pragma unroll
            for (int j = 0; j < 4; j++) a2[i][j] = fmaf(a[i], w[j], a2[i][j]);
    }

    #pragma unroll
    for (int i = 0; i < 4; i++)
        #pragma unroll
        for (int j = 0; j < 4; j++) mts[ty * 4 + i][tx * 4 + j] = a2[i][j];
    __syncthreads();

    const int dcol = tid >> 2;
    const int seg  = (tid & 3) * 16;
    uint32_t hw[8], lw[8];
    #pragma unroll
    for (int u = 0; u < 8; ++u) {
        float x0 = mts[seg + 2 * u][dcol];
        float x1 = mts[seg + 2 * u + 1][dcol];
        __nv_bfloat16 h0, l0, h1, l1;
        split1(x0, h0, l0); split1(x1, h1, l1);
        hw[u] = (uint32_t)__bfloat16_as_ushort(h0) | ((uint32_t)__bfloat16_as_ushort(h1) << 16);
        lw[u] = (uint32_t)__bfloat16_as_ushort(l0) | ((uint32_t)__bfloat16_as_ushort(l1) << 16);
    }
    const size_t o = ((size_t)b * 512 + d0 + dcol) * 512 + h * 64 + seg;
    uint4* ph = reinterpret_cast<uint4*>(&g_Mth[o]);
    uint4* pl = reinterpret_cast<uint4*>(&g_Mtl[o]);
    ph[0] = make_uint4(hw[0], hw[1], hw[2], hw[3]);
    ph[1] = make_uint4(hw[4], hw[5], hw[6], hw[7]);
    pl[0] = make_uint4(lw[0], lw[1], lw[2], lw[3]);
    pl[1] = make_uint4(lw[4], lw[5], lw[6], lw[7]);
}

// =====================================================================
// final GEMM: 128x256, out = q_n @ Mt^T + bo
// =====================================================================
__device__ __forceinline__ void stage_load(
    uint32_t sdst,
    const __nv_bfloat16* __restrict__ Ah, const __nv_bfloat16* __restrict__ Al,
    const __nv_bfloat16* __restrict__ Bh, const __nv_bfloat16* __restrict__ Bl,
    int tid, int m0, int n0, int k0)
{
    #pragma unroll
    for (int j = 0; j < 4; ++j) {
        const int idx = tid + j * 256;
        const int row = idx >> 3, seg = idx & 7;
        const uint32_t d = sdst + (uint32_t)row * 144u + (uint32_t)seg * 16u;
        const size_t g = (size_t)(m0 + row) * 512 + k0 + seg * 8;
        CPA(d + AH_O, Ah + g);
        CPA(d + AL_O, Al + g);
    }
    #pragma unroll
    for (int j = 0; j < 8; ++j) {
        const int idx = tid + j * 256;
        const int row = idx >> 3, seg = idx & 7;
        const uint32_t d = sdst + (uint32_t)row * 144u + (uint32_t)seg * 16u;
        const size_t g = (size_t)(n0 + row) * 512 + k0 + seg * 8;
        CPA(d + BH_O, Bh + g);
        CPA(d + BL_O, Bl + g);
    }
}

__global__ __launch_bounds__(256, 1) void final_gemm_kernel(
    const float* __restrict__ biasIn, float* __restrict__ Cout)
{
    extern __shared__ char smem[];
    const uint32_t sb = smem_u32(smem);
    const int tid = threadIdx.x, lane = tid & 31, warp = tid >> 5;
    const int wm = warp >> 2, wn = warp & 3;
    const int m0 = blockIdx.y * 128, n0 = blockIdx.x * 256;

    const __nv_bfloat16* Agh = g_qsh;
    const __nv_bfloat16* Agl = g_qsl;
    const size_t boff = (size_t)(m0 >> 13) * 512 * 512;
    const __nv_bfloat16* Bgh = g_Mth + boff;
    const __nv_bfloat16* Bgl = g_Mtl + boff;

    float acc[4][8][4];
    #pragma unroll
    for (int i = 0; i < 4; ++i)
        #pragma unroll
        for (int j = 0; j < 8; ++j)
            #pragma unroll
            for (int u = 0; u < 4; ++u) acc[i][j][u] = 0.f;

    const int a_r  = lane & 15;
    const int a_c  = (lane >> 4) << 3;
    const int bg   = lane >> 3;
    const int b_nr = ((bg & 2) << 2) + (lane & 7);
    const int b_ka = (bg & 1) << 3;

    stage_load(sb, Agh, Agl, Bgh, Bgl, tid, m0, n0, 0);
    CPC();

    #pragma unroll 1
    for (int c = 0; c < 8; ++c) {
        if (c < 7) {
            stage_load(sb + (uint32_t)((c + 1) & 1) * STAGE_B, Agh, Agl, Bgh, Bgl,
                       tid, m0, n0, (c + 1) * 64);
            CPC();
            asm volatile("cp.async.wait_group 1;" ::: "memory");
        } else {
            asm volatile("cp.async.wait_group 0;" ::: "memory");
        }
        __syncthreads();

        const uint32_t s0 = sb + (uint32_t)(c & 1) * STAGE_B;
        #pragma unroll
        for (int ks = 0; ks < 4; ++ks) {
            uint32_t ah[4][4], al[4][4];
            #pragma unroll
            for (int mt = 0; mt < 4; ++mt) {
                const uint32_t aoff = (uint32_t)((wm * 64 + mt * 16 + a_r) * 144
                                                 + (ks * 16 + a_c) * 2);
                ldsm4(ah[mt], s0 + AH_O + aoff);
                ldsm4(al[mt], s0 + AL_O + aoff);
            }
            #pragma unroll
            for (int g = 0; g < 4; ++g) {
                const uint32_t boff2 = (uint32_t)((wn * 64 + g * 16 + b_nr) * 144
                                                  + (ks * 16 + b_ka) * 2);
                uint32_t bh4[4], bl4[4];
                ldsm4(bh4, s0 + BH_O + boff2);
                ldsm4(bl4, s0 + BL_O + boff2);
                #pragma unroll
                for (int mt = 0; mt < 4; ++mt) {
                    mma16816(acc[mt][2 * g],     ah[mt], bh4);
                    mma16816(acc[mt][2 * g + 1], ah[mt], bh4 + 2);
                }
                #pragma unroll
                for (int mt = 0; mt < 4; ++mt) {
                    mma16816(acc[mt][2 * g],     ah[mt], bl4);
                    mma16816(acc[mt][2 * g + 1], ah[mt], bl4 + 2);
                }
                #pragma unroll
                for (int mt = 0; mt < 4; ++mt) {
                    mma16816(acc[mt][2 * g],     al[mt], bh4);
                    mma16816(acc[mt][2 * g + 1], al[mt], bh4 + 2);
                }
            }
        }
        __syncthreads();
    }

    const int r0 = m0 + wm * 64 + (lane >> 2);
    const int cg0 = n0 + wn * 64 + (lane & 3) * 2;
    #pragma unroll
    for (int mt = 0; mt < 4; ++mt) {
        #pragma unroll
        for (int nt = 0; nt < 8; ++nt) {
            const int rr = r0 + mt * 16;
            const int cc = cg0 + nt * 8;
            const float bx = biasIn[cc], by = biasIn[cc + 1];
            float* dst = Cout + (size_t)rr * 512 + cc;
            *reinterpret_cast<float2*>(dst) = make_float2(acc[mt][nt][0] + bx, acc[mt][nt][1] + by);
            *reinterpret_cast<float2*>(dst + 8 * 512) = make_float2(acc[mt][nt][2] + bx, acc[mt][nt][3] + by);
        }
    }
}

// =====================================================================
extern "C" void kernel_launch(void* const* d_in, const int* in_sizes, int n_in,
                              void* d_out, int out_size)
{
    const float* X     = (const float*)d_in[0];
    const float* Wq    = (const float*)d_in[1];
    const float* bq    = (const float*)d_in[2];
    const float* Wk    = (const float*)d_in[3];
    const float* bk    = (const float*)d_in[4];
    const float* Wv    = (const float*)d_in[5];
    const float* bv    = (const float*)d_in[6];
    const float* Wo    = (const float*)d_in[7];
    const float* bo    = (const float*)d_in[8];
    const float* gamma = (const float*)d_in[9];
    float* out = (float*)d_out;

    cudaFuncSetAttribute(gram2_kernel,      cudaFuncAttributeMaxDynamicSharedMemorySize, GRAM_SMEM);
    cudaFuncSetAttribute(q_gemm_kernel,     cudaFuncAttributeMaxDynamicSharedMemorySize, GRAM_SMEM);
    cudaFuncSetAttribute(p_gemm_kernel,     cudaFuncAttributeMaxDynamicSharedMemorySize, GRAM_SMEM);
    cudaFuncSetAttribute(final_gemm_kernel, cudaFuncAttributeMaxDynamicSharedMemorySize, DYN_SMEM);
    cudaFuncSetAttribute(kvB_kernel,        cudaFuncAttributeMaxDynamicSharedMemorySize, 51200);

    // side stream + fork/join events (created fresh; host-side only, capturable)
    cudaStream_t s2;
    cudaStreamCreateWithFlags(&s2, cudaStreamNonBlocking);
    cudaEvent_t evFork, evJoin;
    cudaEventCreateWithFlags(&evFork, cudaEventDisableTiming);
    cudaEventCreateWithFlags(&evJoin, cudaEventDisableTiming);

    // main stream: prep + transpose (produce Xh/Xl, Xt, colsum partials)
    prep_w_kernel<<<dim3(16, 48), dim3(32, 8)>>>(Wq, Wk, Wv, bq, bk, bv);
    transpose_pack_kernel<<<dim3(16, 128, 8), dim3(32, 8)>>>(X);

    // fork: side stream handles the kv chain while main runs q projection
    cudaEventRecord(evFork, 0);
    cudaStreamWaitEvent(s2, evFork, 0);

    colsum_reduce_kernel<<<16, 256, 0, s2>>>();
    gram2_kernel<<<640, 256, GRAM_SMEM, s2>>>();
    gram_reduce_kernel<<<2048, 256, 0, s2>>>();
    p_gemm_kernel<<<dim3(4, 32), 256, GRAM_SMEM, s2>>>();
    kvA_kernel<<<64, 256, 0, s2>>>(Wk, Wv, bk, bv);
    kvB_kernel<<<dim3(64, 8), 256, 51200, s2>>>(Wo, gamma);
    cudaEventRecord(evJoin, s2);

    // concurrent on main stream: q projection + fused norm
    q_gemm_kernel<<<2048, 256, GRAM_SMEM>>>(gamma);

    // join, then final GEMM
    cudaStreamWaitEvent(0, evJoin, 0);
    final_gemm_kernel<<<dim3(2, 512), 256, DYN_SMEM>>>(bo, out);

    cudaEventDestroy(evFork);
    cudaEventDestroy(evJoin);
    cudaStreamDestroy(s2);
}

// round 17
// speedup vs baseline: 1.0144x; 1.0144x over previous
#include <cuda_runtime.h>
#include <cuda_bf16.h>
#include <math.h>
#include <stdint.h>

#define B_   8
#define N_   8192
#define D_   512
#define H_   8
#define BN_ROWS 65536

// ---------------- scratch ----------------
__device__ __nv_bfloat16 g_Xh[(size_t)BN_ROWS * D_];
__device__ __nv_bfloat16 g_Xl[(size_t)BN_ROWS * D_];
__device__ __nv_bfloat16 g_Xth[(size_t)BN_ROWS * D_];
__device__ __nv_bfloat16 g_Xtl[(size_t)BN_ROWS * D_];
__device__ __nv_bfloat16 g_qsh[(size_t)BN_ROWS * D_];
__device__ __nv_bfloat16 g_qsl[(size_t)BN_ROWS * D_];
__device__ __nv_bfloat16 g_Bth[1536 * 512];
__device__ __nv_bfloat16 g_Btl[1536 * 512];
__device__ float g_biasC[1536];
__device__ float g_Gp[(size_t)32 * 512 * 512];               // gram partials [b*4+ksp]
__device__ __nv_bfloat16 g_Gh[(size_t)8 * 512 * 512];
__device__ __nv_bfloat16 g_Gl[(size_t)8 * 512 * 512];
__device__ float g_P[(size_t)8 * 512 * 512];
__device__ float g_spart[128 * 4096];
__device__ float g_s[8 * 512];
__device__ float g_kvn[64 * 4096];
__device__ __nv_bfloat16 g_Mth[(size_t)B_ * 512 * 512];
__device__ __nv_bfloat16 g_Mtl[(size_t)B_ * 512 * 512];

// ---------------- helpers ----------------
__device__ __forceinline__ uint32_t smem_u32(const void* p) {
    uint32_t a;
    asm("{ .reg .u64 t; cvta.to.shared.u64 t, %1; cvt.u32.u64 %0, t; }" : "=r"(a) : "l"(p));
    return a;
}
__device__ __forceinline__ void ldsm4(uint32_t* r, uint32_t a) {
    asm volatile("ldmatrix.sync.aligned.m8n8.x4.shared.b16 {%0,%1,%2,%3}, [%4];"
                 : "=r"(r[0]), "=r"(r[1]), "=r"(r[2]), "=r"(r[3]) : "r"(a));
}
__device__ __forceinline__ void mma16816(float* c, const uint32_t* a, const uint32_t* b) {
    asm("mma.sync.aligned.m16n8k16.row.col.f32.bf16.bf16.f32 "
        "{%0,%1,%2,%3}, {%4,%5,%6,%7}, {%8,%9}, {%0,%1,%2,%3};"
        : "+f"(c[0]), "+f"(c[1]), "+f"(c[2]), "+f"(c[3])
        : "r"(a[0]), "r"(a[1]), "r"(a[2]), "r"(a[3]), "r"(b[0]), "r"(b[1]));
}
#define CPA(d, s) asm volatile("cp.async.cg.shared.global [%0], [%1], 16;" :: "r"(d), "l"(s))
#define CPC()     asm volatile("cp.async.commit_group;" ::: "memory")

__device__ __forceinline__ void split1(float x, __nv_bfloat16& h, __nv_bfloat16& l) {
    h = __float2bfloat16(x);
    l = __float2bfloat16(x - __bfloat162float(h));
}

#define AH_O 0u
#define AL_O 18432u
#define BH_O 36864u
#define BL_O 73728u
#define STAGE_B  110592u
#define DYN_SMEM (2 * 110592)

#define GA_H 0u
#define GA_L 10240u
#define GB_H 20480u
#define GB_L 30720u
#define GSTAGE_B 40960u
#define GRAM_SMEM (2 * 40960)

// =====================================================================
// prep_w
// =====================================================================
__global__ void prep_w_kernel(
    const float* __restrict__ Wq, const float* __restrict__ Wk, const float* __restrict__ Wv,
    const float* __restrict__ bq, const float* __restrict__ bk, const float* __restrict__ bv)
{
    __shared__ float tile[32][33];
    const int k0 = blockIdx.x * 32, n0g = blockIdx.y * 32;
    const float* W; const float* bias;
    if (n0g < 512)       { W = Wq; bias = bq; }
    else if (n0g < 1024) { W = Wk; bias = bk; }
    else                 { W = Wv; bias = bv; }
    const int nn0 = n0g & 511;
    const int tx = threadIdx.x, ty = threadIdx.y;
    #pragma unroll
    for (int i = 0; i < 4; ++i)
        tile[ty + i * 8][tx] = W[(size_t)(k0 + ty + i * 8) * 512 + nn0 + tx];
    __syncthreads();
    #pragma unroll
    for (int i = 0; i < 4; ++i) {
        float x = tile[tx][ty + i * 8];
        __nv_bfloat16 h, l; split1(x, h, l);
        size_t o = (size_t)(n0g + ty + i * 8) * 512 + k0 + tx;
        g_Bth[o] = h; g_Btl[o] = l;
    }
    if (blockIdx.x == 0 && ty == 0) g_biasC[n0g + tx] = bias[nn0 + tx];
}

// =====================================================================
// transpose_pack + colsum partials
// =====================================================================
__global__ __launch_bounds__(256) void transpose_pack_kernel(const float* __restrict__ X)
{
    __shared__ ushort sh[32][80];
    __shared__ ushort sl[32][80];
    __shared__ float ps[8][32];
    const int b = blockIdx.z;
    const int d0 = blockIdx.x * 32;
    const int n0 = blockIdx.y * 64;
    const int tx = threadIdx.x, ty = threadIdx.y;

    const float* Xb = X + (size_t)b * N_ * 512;
    ushort* Xh_out = reinterpret_cast<ushort*>(g_Xh);
    ushort* Xl_out = reinterpret_cast<ushort*>(g_Xl);
    float s = 0.f;
    #pragma unroll
    for (int i = 0; i < 8; ++i) {
        const int n = ty + i * 8;
        float x = Xb[(size_t)(n0 + n) * 512 + d0 + tx];
        s += x;
        __nv_bfloat16 h, l; split1(x, h, l);
        const ushort hu = __bfloat16_as_ushort(h);
        const ushort lu = __bfloat16_as_ushort(l);
        sh[tx][n] = hu;
        sl[tx][n] = lu;
        const size_t on = ((size_t)b * N_ + n0 + n) * 512 + d0 + tx;
        Xh_out[on] = hu;
        Xl_out[on] = lu;
    }
    ps[ty][tx] = s;
    __syncthreads();

    const int t = ty * 32 + tx;
    const int d = t >> 3;
    const int ng = t & 7;
    uint4 hv = *reinterpret_cast<const uint4*>(&sh[d][ng * 8]);
    uint4 lv = *reinterpret_cast<const uint4*>(&sl[d][ng * 8]);
    const size_t o = ((size_t)b * 512 + d0 + d) * N_ + n0 + ng * 8;
    *reinterpret_cast<uint4*>(&g_Xth[o]) = hv;
    *reinterpret_cast<uint4*>(&g_Xtl[o]) = lv;

    if (ty == 0) {
        float cs = 0.f;
        #pragma unroll
        for (int j = 0; j < 8; ++j) cs += ps[j][tx];
        g_spart[(size_t)blockIdx.y * 4096 + b * 512 + d0 + tx] = cs;
    }
}

// =====================================================================
// 128x128 gemm: stage loader + core (warp 64x32, k-chunk 32)
// =====================================================================
__device__ __forceinline__ void gstage_load(
    uint32_t sdst,
    const __nv_bfloat16* __restrict__ Ah, const __nv_bfloat16* __restrict__ Al,
    const __nv_bfloat16* __restrict__ Bh, const __nv_bfloat16* __restrict__ Bl,
    int tid, int m0, int n0, int k0, size_t lda, size_t ldb)
{
    #pragma unroll
    for (int j = 0; j < 2; ++j) {
        const int idx = tid + j * 256;
        const int row = idx >> 2, seg = idx & 3;
        const uint32_t d = sdst + (uint32_t)row * 80u + (uint32_t)seg * 16u;
        CPA(d + GA_H, Ah + (size_t)(m0 + row) * lda + k0 + seg * 8);
        CPA(d + GA_L, Al + (size_t)(m0 + row) * lda + k0 + seg * 8);
        CPA(d + GB_H, Bh + (size_t)(n0 + row) * ldb + k0 + seg * 8);
        CPA(d + GB_L, Bl + (size_t)(n0 + row) * ldb + k0 + seg * 8);
    }
}

__device__ __forceinline__ void gemm128_core(
    uint32_t sb, float acc[4][4][4],
    const __nv_bfloat16* Ah, const __nv_bfloat16* Al,
    const __nv_bfloat16* Bh, const __nv_bfloat16* Bl,
    int tid, int m0, int n0, int kbase, int nch, size_t lda, size_t ldb)
{
    const int lane = tid & 31, warp = tid >> 5;
    const int wm = warp >> 2, wn = warp & 3;
    const int a_r  = lane & 15;
    const int a_c  = (lane >> 4) << 3;
    const int bg   = lane >> 3;
    const int b_nr = ((bg & 2) << 2) + (lane & 7);
    const int b_ka = (bg & 1) << 3;

    gstage_load(sb, Ah, Al, Bh, Bl, tid, m0, n0, kbase, lda, ldb);
    CPC();

    #pragma unroll 1
    for (int c = 0; c < nch; ++c) {
        if (c < nch - 1) {
            gstage_load(sb + (uint32_t)((c + 1) & 1) * GSTAGE_B, Ah, Al, Bh, Bl,
                        tid, m0, n0, kbase + (c + 1) * 32, lda, ldb);
            CPC();
            asm volatile("cp.async.wait_group 1;" ::: "memory");
        } else {
            asm volatile("cp.async.wait_group 0;" ::: "memory");
        }
        __syncthreads();

        const uint32_t s0 = sb + (uint32_t)(c & 1) * GSTAGE_B;
        #pragma unroll
        for (int ks = 0; ks < 2; ++ks) {
            uint32_t ah[4][4], al[4][4];
            #pragma unroll
            for (int mt = 0; mt < 4; ++mt) {
                const uint32_t aoff = (uint32_t)((wm * 64 + mt * 16 + a_r) * 80
                                                 + (ks * 16 + a_c) * 2);
                ldsm4(ah[mt], s0 + GA_H + aoff);
                ldsm4(al[mt], s0 + GA_L + aoff);
            }
            #pragma unroll
            for (int g = 0; g < 2; ++g) {
                const uint32_t boff = (uint32_t)((wn * 32 + g * 16 + b_nr) * 80
                                                 + (ks * 16 + b_ka) * 2);
                uint32_t bh4[4], bl4[4];
                ldsm4(bh4, s0 + GB_H + boff);
                ldsm4(bl4, s0 + GB_L + boff);
                #pragma unroll
                for (int mt = 0; mt < 4; ++mt) {
                    mma16816(acc[mt][2 * g],     ah[mt], bh4);
                    mma16816(acc[mt][2 * g + 1], ah[mt], bh4 + 2);
                }
                #pragma unroll
                for (int mt = 0; mt < 4; ++mt) {
                    mma16816(acc[mt][2 * g],     ah[mt], bl4);
                    mma16816(acc[mt][2 * g + 1], ah[mt], bl4 + 2);
                }
                #pragma unroll
                for (int mt = 0; mt < 4; ++mt) {
                    mma16816(acc[mt][2 * g],     al[mt], bh4);
                    mma16816(acc[mt][2 * g + 1], al[mt], bh4 + 2);
                }
            }
        }
        __syncthreads();
    }
}

// =====================================================================
// gq: merged gram (320 CTAs, split-K=4, scheduled first) + q projection
// with fused norm (2048 CTAs). grid = 2368 flat, 2 CTAs/SM.
// =====================================================================
__global__ __launch_bounds__(256, 2) void gq_kernel(const float* __restrict__ gammaIn)
{
    extern __shared__ char smem[];
    const uint32_t sb = smem_u32(smem);
    const int tid = threadIdx.x, lane = tid & 31, warp = tid >> 5;
    const int wm = warp >> 2, wn = warp & 3;

    float acc[4][4][4];
    #pragma unroll
    for (int i = 0; i < 4; ++i)
        #pragma unroll
        for (int j = 0; j < 4; ++j)
            #pragma unroll
            for (int u = 0; u < 4; ++u) acc[i][j][u] = 0.f;

    if (blockIdx.x < 320) {
        // ---------------- gram tile (K-slice 2048, 64 chunks) ----------------
        const int g = blockIdx.x;
        const int b = g / 40;
        const int rem = g - b * 40;
        const int ksp = rem / 10;
        const int ti = rem - ksp * 10;
        int tym = 0;
        while ((tym + 1) * (tym + 2) / 2 <= ti) ++tym;
        const int txm = ti - tym * (tym + 1) / 2;
        const int m0 = tym * 128, n0 = txm * 128;
        const bool mirror = (tym != txm);

        const __nv_bfloat16* Xh = g_Xth + (size_t)b * 512 * 8192;
        const __nv_bfloat16* Xl = g_Xtl + (size_t)b * 512 * 8192;
        float* gpout = g_Gp + (size_t)(b * 4 + ksp) * 262144;

        gemm128_core(sb, acc, Xh, Xl, Xh, Xl, tid, m0, n0, ksp * 2048, 64, 8192, 8192);

        const int r0 = m0 + wm * 64 + (lane >> 2);
        const int cg0 = n0 + wn * 32 + (lane & 3) * 2;
        #pragma unroll
        for (int mt = 0; mt < 4; ++mt) {
            #pragma unroll
            for (int nt = 0; nt < 4; ++nt) {
                const int rr = r0 + mt * 16;
                const int cc = cg0 + nt * 8;
                float* dst = gpout + (size_t)rr * 512 + cc;
                *reinterpret_cast<float2*>(dst) = make_float2(acc[mt][nt][0], acc[mt][nt][1]);
                *reinterpret_cast<float2*>(dst + 8 * 512) = make_float2(acc[mt][nt][2], acc[mt][nt][3]);
                if (mirror) {
                    gpout[(size_t)cc * 512 + rr]           = acc[mt][nt][0];
                    gpout[(size_t)(cc + 1) * 512 + rr]     = acc[mt][nt][1];
                    gpout[(size_t)cc * 512 + rr + 8]       = acc[mt][nt][2];
                    gpout[(size_t)(cc + 1) * 512 + rr + 8] = acc[mt][nt][3];
                }
            }
        }
    } else {
        // ---------------- q tile + fused norm ----------------
        const int idx = blockIdx.x - 320;
        const int m0 = (idx >> 2) * 128, n0 = (idx & 3) * 128;

        gemm128_core(sb, acc, g_Xh, g_Xl, g_Bth, g_Btl, tid, m0, n0, 0, 16, 512, 512);

        float* part = reinterpret_cast<float*>(smem);
        const float gam = gammaIn[(n0 + wn * 32) >> 6];
        const int r_l = lane >> 2;
        const int cg0 = n0 + wn * 32 + (lane & 3) * 2;
        float sums[8], sc_arr[8];
        #pragma unroll
        for (int mt = 0; mt < 4; ++mt) {
            #pragma unroll
            for (int z = 0; z < 2; ++z) {
                float s = 0.f;
                #pragma unroll
                for (int nt = 0; nt < 4; ++nt) {
                    const int cc = cg0 + nt * 8;
                    float x0 = acc[mt][nt][2 * z]     + g_biasC[cc];
                    float x1 = acc[mt][nt][2 * z + 1] + g_biasC[cc + 1];
                    acc[mt][nt][2 * z] = x0; acc[mt][nt][2 * z + 1] = x1;
                    s = fmaf(x0, x0, s); s = fmaf(x1, x1, s);
                }
                s += __shfl_xor_sync(0xffffffffu, s, 1);
                s += __shfl_xor_sync(0xffffffffu, s, 2);
                sums[mt * 2 + z] = s;
            }
        }
        #pragma unroll
        for (int mt = 0; mt < 4; ++mt)
            #pragma unroll
            for (int z = 0; z < 2; ++z)
                if ((lane & 3) == 0) {
                    const int rt = wm * 64 + mt * 16 + z * 8 + r_l;
                    part[rt * 4 + wn] = sums[mt * 2 + z];
                }
        __syncthreads();
        #pragma unroll
        for (int mt = 0; mt < 4; ++mt)
            #pragma unroll
            for (int z = 0; z < 2; ++z) {
                const int rt = wm * 64 + mt * 16 + z * 8 + r_l;
                const float s2 = part[rt * 4 + wn] + part[rt * 4 + (wn ^ 1)];
                sc_arr[mt * 2 + z] = gam / sqrtf(s2);
            }
        #pragma unroll
        for (int mt = 0; mt < 4; ++mt) {
            #pragma unroll
            for (int z = 0; z < 2; ++z) {
                const int rr = m0 + wm * 64 + mt * 16 + z * 8 + r_l;
                const float sc = sc_arr[mt * 2 + z];
                #pragma unroll
                for (int nt = 0; nt < 4; ++nt) {
                    __nv_bfloat16 h0, l0, h1, l1;
                    split1(acc[mt][nt][2 * z] * sc, h0, l0);
                    split1(acc[mt][nt][2 * z + 1] * sc, h1, l1);
                    const uint32_t hw = (uint32_t)__bfloat16_as_ushort(h0)
                                      | ((uint32_t)__bfloat16_as_ushort(h1) << 16);
                    const uint32_t lw = (uint32_t)__bfloat16_as_ushort(l0)
                                      | ((uint32_t)__bfloat16_as_ushort(l1) << 16);
                    const size_t o = (size_t)rr * 512 + cg0 + nt * 8;
                    *reinterpret_cast<uint32_t*>(&g_qsh[o]) = hw;
                    *reinterpret_cast<uint32_t*>(&g_qsl[o]) = lw;
                }
            }
        }
    }
}

// =====================================================================
// reduce_combined: blocks [0,2048) gram reduce+split; [2048,2064) colsum
// =====================================================================
__global__ __launch_bounds__(256) void reduce_combined_kernel()
{
    if (blockIdx.x < 2048) {
        const size_t gid = (size_t)blockIdx.x * 256 + threadIdx.x;
        const int b = (int)(gid >> 16);
        const size_t e = (gid & 65535) * 4;
        float4 s = make_float4(0.f, 0.f, 0.f, 0.f);
        #pragma unroll
        for (int p = 0; p < 4; ++p) {
            float4 t = *reinterpret_cast<const float4*>(
                &g_Gp[((size_t)(b * 4 + p)) * 262144 + e]);
            s.x += t.x; s.y += t.y; s.z += t.z; s.w += t.w;
        }
        __nv_bfloat16 h0, l0, h1, l1, h2, l2, h3, l3;
        split1(s.x, h0, l0); split1(s.y, h1, l1); split1(s.z, h2, l2); split1(s.w, h3, l3);
        uint2 hv, lv;
        hv.x = (uint32_t)__bfloat16_as_ushort(h0) | ((uint32_t)__bfloat16_as_ushort(h1) << 16);
        hv.y = (uint32_t)__bfloat16_as_ushort(h2) | ((uint32_t)__bfloat16_as_ushort(h3) << 16);
        lv.x = (uint32_t)__bfloat16_as_ushort(l0) | ((uint32_t)__bfloat16_as_ushort(l1) << 16);
        lv.y = (uint32_t)__bfloat16_as_ushort(l2) | ((uint32_t)__bfloat16_as_ushort(l3) << 16);
        const size_t o = (size_t)b * 262144 + e;
        *reinterpret_cast<uint2*>(&g_Gh[o]) = hv;
        *reinterpret_cast<uint2*>(&g_Gl[o]) = lv;
    } else {
        const int out = (blockIdx.x - 2048) * 256 + threadIdx.x;   // 4096
        float s = 0.f;
        #pragma unroll 8
        for (int j = 0; j < 128; ++j) s += g_spart[(size_t)j * 4096 + out];
        g_s[out] = s;
    }
}

// =====================================================================
// p_gemm: P = G @ Wv, 128x128, 2 CTAs/SM. grid (4, 32)
// =====================================================================
__global__ __launch_bounds__(256, 2) void p_gemm_kernel()
{
    extern __shared__ char smem[];
    const uint32_t sb = smem_u32(smem);
    const int tid = threadIdx.x, lane = tid & 31, warp = tid >> 5;
    const int wm = warp >> 2, wn = warp & 3;
    const int m0 = blockIdx.y * 128, n0 = blockIdx.x * 128;

    const __nv_bfloat16* Bh = g_Bth + (size_t)1024 * 512;
    const __nv_bfloat16* Bl = g_Btl + (size_t)1024 * 512;

    float acc[4][4][4];
    #pragma unroll
    for (int i = 0; i < 4; ++i)
        #pragma unroll
        for (int j = 0; j < 4; ++j)
            #pragma unroll
            for (int u = 0; u < 4; ++u) acc[i][j][u] = 0.f;

    gemm128_core(sb, acc, g_Gh, g_Gl, Bh, Bl, tid, m0, n0, 0, 16, 512, 512);

    const int r0 = m0 + wm * 64 + (lane >> 2);
    const int cg0 = n0 + wn * 32 + (lane & 3) * 2;
    #pragma unroll
    for (int mt = 0; mt < 4; ++mt) {
        #pragma unroll
        for (int nt = 0; nt < 4; ++nt) {
            const int rr = r0 + mt * 16;
            const int cc = cg0 + nt * 8;
            float* dst = g_P + (size_t)rr * 512 + cc;
            *reinterpret_cast<float2*>(dst) = make_float2(acc[mt][nt][0], acc[mt][nt][1]);
            *reinterpret_cast<float2*>(dst + 8 * 512) = make_float2(acc[mt][nt][2], acc[mt][nt][3]);
        }
    }
}

// =====================================================================
// kvA: kv = Wk_h^T P + rank-1 bias terms; row-normalize -> g_kvn
// =====================================================================
__global__ __launch_bounds__(256) void kvA_kernel(
    const float* __restrict__ Wk, const float* __restrict__ Wv,
    const float* __restrict__ bk, const float* __restrict__ bv)
{
    __shared__ float wk_s[16][68];
    __shared__ float p_s[16][68];
    __shared__ float kvs[64][65];
    __shared__ float rs[64];
    __shared__ float corr_k[64];
    __shared__ float corr_v[64];
    __shared__ float cpart[256];

    const int bh = blockIdx.x, b = bh >> 3, h = bh & 7;
    const int tid = threadIdx.x;
    const int tx = tid & 15, ty = tid >> 4;
    const int lr = tid >> 4, lc4 = (tid & 15) << 2;

    float acc[4][4];
    #pragma unroll
    for (int i = 0; i < 4; ++i)
        #pragma unroll
        for (int j = 0; j < 4; ++j) acc[i][j] = 0.f;

    for (int k0 = 0; k0 < 512; k0 += 16) {
        *reinterpret_cast<float4*>(&wk_s[lr][lc4]) =
            *reinterpret_cast<const float4*>(&Wk[(size_t)(k0 + lr) * 512 + h * 64 + lc4]);
        *reinterpret_cast<float4*>(&p_s[lr][lc4]) =
            *reinterpret_cast<const float4*>(&g_P[((size_t)b * 512 + k0 + lr) * 512 + h * 64 + lc4]);
        __syncthreads();
        #pragma unroll
        for (int kk = 0; kk < 16; ++kk) {
            float a[4], w[4];
            #pragma unroll
            for (int i = 0; i < 4; ++i) a[i] = wk_s[kk][ty * 4 + i];
            #pragma unroll
            for (int j = 0; j < 4; ++j) w[j] = p_s[kk][tx * 4 + j];
            #pragma unroll
            for (int i = 0; i < 4; ++i)
                #pragma unroll
                for (int j = 0; j < 4; ++j) acc[i][j] = fmaf(a[i], w[j], acc[i][j]);
        }
        __syncthreads();
    }

    {
        const int out = tid & 127;
        const int half = tid >> 7;
        const int idx = out & 63;
        const float* Wx = (out < 64) ? Wk : Wv;
        float s = 0.f;
        const int d0 = half * 256;
        for (int d = d0; d < d0 + 256; ++d)
            s = fmaf(g_s[b * 512 + d], Wx[(size_t)d * 512 + h * 64 + idx], s);
        cpart[half * 128 + out] = s;
    }
    __syncthreads();
    if (tid < 64) corr_k[tid] = cpart[tid] + cpart[128 + tid];
    else if (tid < 128) corr_v[tid - 64] = cpart[tid] + cpart[128 + tid];
    __syncthreads();

    #pragma unroll
    for (int i = 0; i < 4; ++i) {
        const int dk = ty * 4 + i;
        const float bkk = bk[h * 64 + dk];
        const float ck = corr_k[dk];
        #pragma unroll
        for (int j = 0; j < 4; ++j) {
            const int dv = tx * 4 + j;
            const float bvv = bv[h * 64 + dv];
            kvs[dk][dv] = acc[i][j] + ck * bvv + bkk * (corr_v[dv] + 8192.0f * bvv);
        }
    }
    __syncthreads();

    if (tid < 64) {
        float s = 0.f;
        #pragma unroll
        for (int c = 0; c < 64; ++c) { float x = kvs[tid][c]; s = fmaf(x, x, s); }
        rs[tid] = 1.0f / sqrtf(s);
    }
    __syncthreads();

    for (int idx = tid; idx < 4096; idx += 256) {
        const int dk = idx >> 6, dv = idx & 63;
        g_kvn[(size_t)bh * 4096 + idx] = kvs[dk][dv] * rs[dk];
    }
}

// =====================================================================
// kvB: Wo fold -> Mt (bf16 split). grid (64 bh, 8 dt)
// =====================================================================
__global__ __launch_bounds__(256) void kvB_kernel(
    const float* __restrict__ Wo, const float* __restrict__ gamma)
{
    extern __shared__ float dsm[];
    float (*kvn)[65] = reinterpret_cast<float(*)[65]>(dsm);
    float (*wos)[65] = reinterpret_cast<float(*)[65]>(dsm + 4160);
    float (*mts)[65] = reinterpret_cast<float(*)[65]>(dsm + 8320);

    const int bh = blockIdx.x, b = bh >> 3, h = bh & 7;
    const int dt = blockIdx.y;
    const int d0 = dt * 64;
    const int tid = threadIdx.x;
    const int tx = tid & 15, ty = tid >> 4;
    const float gam = gamma[h];

    for (int idx = tid; idx < 4096; idx += 256) {
        kvn[idx >> 6][idx & 63] = g_kvn[(size_t)bh * 4096 + idx] * gam;
        const int dv = idx >> 6, dd = idx & 63;
        wos[dv][dd] = Wo[(size_t)(h * 64 + dv) * 512 + d0 + dd];
    }
    __syncthreads();

    float a2[4][4];
    #pragma unroll
    for (int i = 0; i < 4; i++)
        #pragma unroll
        for (int j = 0; j < 4; j++) a2[i][j] = 0.f;

    #pragma unroll 8
    for (int dv = 0; dv < 64; dv++) {
        float a[4], w[4];
        #pragma unroll
        for (int i = 0; i < 4; i++) a[i] = kvn[ty * 4 + i][dv];
        #pragma unroll
        for (int j = 0; j < 4; j++) w[j] = wos[dv][tx * 4 + j];
        #pragma unroll
        for (int i = 0; i < 4; i++)
            #pragma unroll
            for (int j = 0; j < 4; j++) a2[i][j] = fmaf(a[i], w[j], a2[i][j]);
    }

    #pragma unroll
    for (int i = 0; i < 4; i++)
        #pragma unroll
        for (int j = 0; j < 4; j++) mts[ty * 4 + i][tx * 4 + j] = a2[i][j];
    __syncthreads();

    const int dcol = tid >> 2;
    const int seg  = (tid & 3) * 16;
    uint32_t hw[8], lw[8];
    #pragma unroll
    for (int u = 0; u < 8; ++u) {
        float x0 = mts[seg + 2 * u][dcol];
        float x1 = mts[seg + 2 * u + 1][dcol];
        __nv_bfloat16 h0, l0, h1, l1;
        split1(x0, h0, l0); split1(x1, h1, l1);
        hw[u] = (uint32_t)__bfloat16_as_ushort(h0) | ((uint32_t)__bfloat16_as_ushort(h1) << 16);
        lw[u] = (uint32_t)__bfloat16_as_ushort(l0) | ((uint32_t)__bfloat16_as_ushort(l1) << 16);
    }
    const size_t o = ((size_t)b * 512 + d0 + dcol) * 512 + h * 64 + seg;
    uint4* ph = reinterpret_cast<uint4*>(&g_Mth[o]);
    uint4* pl = reinterpret_cast<uint4*>(&g_Mtl[o]);
    ph[0] = make_uint4(hw[0], hw[1], hw[2], hw[3]);
    ph[1] = make_uint4(hw[4], hw[5], hw[6], hw[7]);
    pl[0] = make_uint4(lw[0], lw[1], lw[2], lw[3]);
    pl[1] = make_uint4(lw[4], lw[5], lw[6], lw[7]);
}

// =====================================================================
// final GEMM: 128x256, out = q_n @ Mt^T + bo
// =====================================================================
__device__ __forceinline__ void stage_load(
    uint32_t sdst,
    const __nv_bfloat16* __restrict__ Ah, const __nv_bfloat16* __restrict__ Al,
    const __nv_bfloat16* __restrict__ Bh, const __nv_bfloat16* __restrict__ Bl,
    int tid, int m0, int n0, int k0)
{
    #pragma unroll
    for (int j = 0; j < 4; ++j) {
        const int idx = tid + j * 256;
        const int row = idx >> 3, seg = idx & 7;
        const uint32_t d = sdst + (uint32_t)row * 144u + (uint32_t)seg * 16u;
        const size_t g = (size_t)(m0 + row) * 512 + k0 + seg * 8;
        CPA(d + AH_O, Ah + g);
        CPA(d + AL_O, Al + g);
    }
    #pragma unroll
    for (int j = 0; j < 8; ++j) {
        const int idx = tid + j * 256;
        const int row = idx >> 3, seg = idx & 7;
        const uint32_t d = sdst + (uint32_t)row * 144u + (uint32_t)seg * 16u;
        const size_t g = (size_t)(n0 + row) * 512 + k0 + seg * 8;
        CPA(d + BH_O, Bh + g);
        CPA(d + BL_O, Bl + g);
    }
}

__global__ __launch_bounds__(256, 1) void final_gemm_kernel(
    const float* __restrict__ biasIn, float* __restrict__ Cout)
{
    extern __shared__ char smem[];
    const uint32_t sb = smem_u32(smem);
    const int tid = threadIdx.x, lane = tid & 31, warp = tid >> 5;
    const int wm = warp >> 2, wn = warp & 3;
    const int m0 = blockIdx.y * 128, n0 = blockIdx.x * 256;

    const __nv_bfloat16* Agh = g_qsh;
    const __nv_bfloat16* Agl = g_qsl;
    const size_t boff = (size_t)(m0 >> 13) * 512 * 512;
    const __nv_bfloat16* Bgh = g_Mth + boff;
    const __nv_bfloat16* Bgl = g_Mtl + boff;

    float acc[4][8][4];
    #pragma unroll
    for (int i = 0; i < 4; ++i)
        #pragma unroll
        for (int j = 0; j < 8; ++j)
            #pragma unroll
            for (int u = 0; u < 4; ++u) acc[i][j][u] = 0.f;

    const int a_r  = lane & 15;
    const int a_c  = (lane >> 4) << 3;
    const int bg   = lane >> 3;
    const int b_nr = ((bg & 2) << 2) + (lane & 7);
    const int b_ka = (bg & 1) << 3;

    stage_load(sb, Agh, Agl, Bgh, Bgl, tid, m0, n0, 0);
    CPC();

    #pragma unroll 1
    for (int c = 0; c < 8; ++c) {
        if (c < 7) {
            stage_load(sb + (uint32_t)((c + 1) & 1) * STAGE_B, Agh, Agl, Bgh, Bgl,
                       tid, m0, n0, (c + 1) * 64);
            CPC();
            asm volatile("cp.async.wait_group 1;" ::: "memory");
        } else {
            asm volatile("cp.async.wait_group 0;" ::: "memory");
        }
        __syncthreads();

        const uint32_t s0 = sb + (uint32_t)(c & 1) * STAGE_B;
        #pragma unroll
        for (int ks = 0; ks < 4; ++ks) {
            uint32_t ah[4][4], al[4][4];
            #pragma unroll
            for (int mt = 0; mt < 4; ++mt) {
                const uint32_t aoff = (uint32_t)((wm * 64 + mt * 16 + a_r) * 144
                                                 + (ks * 16 + a_c) * 2);
                ldsm4(ah[mt], s0 + AH_O + aoff);
                ldsm4(al[mt], s0 + AL_O + aoff);
            }
            #pragma unroll
            for (int g = 0; g < 4; ++g) {
                const uint32_t boff2 = (uint32_t)((wn * 64 + g * 16 + b_nr) * 144
                                                  + (ks * 16 + b_ka) * 2);
                uint32_t bh4[4], bl4[4];
                ldsm4(bh4, s0 + BH_O + boff2);
                ldsm4(bl4, s0 + BL_O + boff2);
                #pragma unroll
                for (int mt = 0; mt < 4; ++mt) {
                    mma16816(acc[mt][2 * g],     ah[mt], bh4);
                    mma16816(acc[mt][2 * g + 1], ah[mt], bh4 + 2);
                }
                #pragma unroll
                for (int mt = 0; mt < 4; ++mt) {
                    mma16816(acc[mt][2 * g],     ah[mt], bl4);
                    mma16816(acc[mt][2 * g + 1], ah[mt], bl4 + 2);
                }
                #pragma unroll
                for (int mt = 0; mt < 4; ++mt) {
                    mma16816(acc[mt][2 * g],     al[mt], bh4);
                    mma16816(acc[mt][2 * g + 1], al[mt], bh4 + 2);
                }
            }
        }
        __syncthreads();
    }

    const int r0 = m0 + wm * 64 + (lane >> 2);
    const int cg0 = n0 + wn * 64 + (lane & 3) * 2;
    #pragma unroll
    for (int mt = 0; mt < 4; ++mt) {
        #pragma unroll
        for (int nt = 0; nt < 8; ++nt) {
            const int rr = r0 + mt * 16;
            const int cc = cg0 + nt * 8;
            const float bx = biasIn[cc], by = biasIn[cc + 1];
            float* dst = Cout + (size_t)rr * 512 + cc;
            *reinterpret_cast<float2*>(dst) = make_float2(acc[mt][nt][0] + bx, acc[mt][nt][1] + by);
            *reinterpret_cast<float2*>(dst + 8 * 512) = make_float2(acc[mt][nt][2] + bx, acc[mt][nt][3] + by);
        }
    }
}

// =====================================================================
extern "C" void kernel_launch(void* const* d_in, const int* in_sizes, int n_in,
                              void* d_out, int out_size)
{
    const float* X     = (const float*)d_in[0];
    const float* Wq    = (const float*)d_in[1];
    const float* bq    = (const float*)d_in[2];
    const float* Wk    = (const float*)d_in[3];
    const float* bk    = (const float*)d_in[4];
    const float* Wv    = (const float*)d_in[5];
    const float* bv    = (const float*)d_in[6];
    const float* Wo    = (const float*)d_in[7];
    const float* bo    = (const float*)d_in[8];
    const float* gamma = (const float*)d_in[9];
    float* out = (float*)d_out;

    cudaFuncSetAttribute(gq_kernel,         cudaFuncAttributeMaxDynamicSharedMemorySize, GRAM_SMEM);
    cudaFuncSetAttribute(p_gemm_kernel,     cudaFuncAttributeMaxDynamicSharedMemorySize, GRAM_SMEM);
    cudaFuncSetAttribute(final_gemm_kernel, cudaFuncAttributeMaxDynamicSharedMemorySize, DYN_SMEM);
    cudaFuncSetAttribute(kvB_kernel,        cudaFuncAttributeMaxDynamicSharedMemorySize, 51200);

    // 1) transpose+split weights, pack biases
    prep_w_kernel<<<dim3(16, 48), dim3(32, 8)>>>(Wq, Wk, Wv, bq, bk, bv);
    // 2) fused split + transpose + colsum partials
    transpose_pack_kernel<<<dim3(16, 128, 8), dim3(32, 8)>>>(X);
    // 3) merged gram (320 CTAs, split-K=4, first) + q projection  [ncu slot... #3]
    gq_kernel<<<2368, 256, GRAM_SMEM>>>(gamma);
    // 4) combined gram reduce+split + colsum reduce
    reduce_combined_kernel<<<2064, 256>>>();
    // 5) P = G @ Wv
    p_gemm_kernel<<<dim3(4, 32), 256, GRAM_SMEM>>>();
    // 6) kv assembly + norm -> kv_n
    kvA_kernel<<<64, 256>>>(Wk, Wv, bk, bv);
    // 7) Wo fold -> Mt
    kvB_kernel<<<dim3(64, 8), 256, 51200>>>(Wo, gamma);
    // 8) out = q_n @ Mt^T + bo
    final_gemm_kernel<<<dim3(2, 512), 256, DYN_SMEM>>>(bo, out);
}